// round 7
// baseline (speedup 1.0000x reference)
#include <cuda_runtime.h>

#define NQ 4
#define BATCH 128
#define PATCHES 196          // 14*14
#define FEAT 784
#define H1 64
#define NOUT 10

// ---------------------------------------------------------------------------
// One fused kernel: block b handles batch row b.
//  Phase 1a: threads 0..195 run the 4-qubit circuit for patch t.
//            Encoding + first YZY layer done on per-qubit 2-amp states
//            (product state), tensored to 16 amps before first CNOT ring.
//  Phase 1b: threads 224..511 (9 warps) prefetch fc1_w/fc2_w into L1.
//  Phase 2:  all 512 threads FC1 (8 threads/neuron, 4 accumulators) + ReLU.
//  Phase 3:  10 warps FC2.
// ---------------------------------------------------------------------------
__global__ void __launch_bounds__(512) fused_kernel(
    const float* __restrict__ x, const float* __restrict__ w,
    const float* __restrict__ fc1_w, const float* __restrict__ fc1_b,
    const float* __restrict__ fc2_w, const float* __restrict__ fc2_b,
    float* __restrict__ out)
{
    __shared__ float cw[60];
    __shared__ float sw[60];
    __shared__ float feat_s[FEAT];
    __shared__ float h_s[H1];

    int b = blockIdx.x;
    int t = threadIdx.x;

    if (t < 60) {
        float s, c;
        sincosf(0.5f * w[t], &s, &c);
        cw[t] = c;
        sw[t] = s;
    }
    __syncthreads();

    if (t < PATCHES) {
        // ---------------- Phase 1a: circuit, one patch per thread -----------
        int i = t / 14;
        int j = t % 14;
        const float* xb = x + b * FEAT;
        const float PI_F = 3.14159265358979323846f;  // (2*pi*x)/2
        float angs[4];
        angs[0] = PI_F * xb[(2*i)  *28 + 2*j    ];
        angs[1] = PI_F * xb[(2*i)  *28 + 2*j + 1];
        angs[2] = PI_F * xb[(2*i+1)*28 + 2*j    ];
        angs[3] = PI_F * xb[(2*i+1)*28 + 2*j + 1];

        // Per-qubit 2-amp states through Rx + layer-0 Ry,Rz,Ry (all 1-qubit)
        float q0r[4], q0i[4], q1r[4], q1i[4];   // [q][amp] packed: a0,a1 per q
        float a0r[4], a0i[4], a1r[4], a1i[4];
#pragma unroll
        for (int q = 0; q < 4; q++) {
            float s, c;
            __sincosf(angs[q], &s, &c);
            // Rx|0> = (c, -i s)
            float xr0 = c,    xi0 = 0.0f;
            float xr1 = 0.0f, xi1 = -s;
            // Ry(p[q]) real rotation
            float c1 = cw[q], s1 = sw[q];
            float yr0 = c1*xr0 - s1*xr1, yi0 = c1*xi0 - s1*xi1;
            float yr1 = s1*xr0 + c1*xr1, yi1 = s1*xi0 + c1*xi1;
            // Rz(p[4+q]): a0 *= (c2,-s2), a1 *= (c2,+s2)
            float c2 = cw[4+q], s2 = sw[4+q];
            float zr0 = yr0*c2 + yi0*s2, zi0 = yi0*c2 - yr0*s2;
            float zr1 = yr1*c2 - yi1*s2, zi1 = yi1*c2 + yr1*s2;
            // Ry(p[8+q])
            float c3 = cw[8+q], s3 = sw[8+q];
            a0r[q] = c3*zr0 - s3*zr1;  a0i[q] = c3*zi0 - s3*zi1;
            a1r[q] = s3*zr0 + c3*zr1;  a1i[q] = s3*zi0 + c3*zi1;
        }

        // Tensor up: u = a(q0) (x) a(q1), v = a(q2) (x) a(q3), amp = u (x) v
        float ur[4], ui[4], vr[4], vi[4];
#pragma unroll
        for (int i0 = 0; i0 < 2; i0++)
#pragma unroll
            for (int i1 = 0; i1 < 2; i1++) {
                float xr = i0 ? a1r[0] : a0r[0], xi = i0 ? a1i[0] : a0i[0];
                float yr = i1 ? a1r[1] : a0r[1], yi = i1 ? a1i[1] : a0i[1];
                ur[i0*2+i1] = xr*yr - xi*yi;
                ui[i0*2+i1] = xr*yi + xi*yr;
                float zr = i0 ? a1r[2] : a0r[2], zi = i0 ? a1i[2] : a0i[2];
                float wr = i1 ? a1r[3] : a0r[3], wi = i1 ? a1i[3] : a0i[3];
                vr[i0*2+i1] = zr*wr - zi*wi;
                vi[i0*2+i1] = zr*wi + zi*wr;
            }

        float sr[16], si[16];
#pragma unroll
        for (int k = 0; k < 16; k++) {
            float xr = ur[k >> 2], xi = ui[k >> 2];
            float yr = vr[k & 3],  yi = vi[k & 3];
            sr[k] = xr*yr - xi*yi;
            si[k] = xr*yi + xi*yr;
        }
        (void)q0r; (void)q0i; (void)q1r; (void)q1i;

        // First CNOT ring (after layer 0), then layers 1..4
#pragma unroll
        for (int q = 0; q < 4; q++) {
            int cmask = 1 << (3 - q);
            int tmask = 1 << (3 - ((q + 1) & 3));
#pragma unroll
            for (int k = 0; k < 16; k++) {
                if ((k & cmask) && !(k & tmask)) {
                    int k1 = k | tmask;
                    float tr = sr[k]; sr[k] = sr[k1]; sr[k1] = tr;
                    float ti = si[k]; si[k] = si[k1]; si[k1] = ti;
                }
            }
        }

#pragma unroll
        for (int layer = 1; layer < 5; layer++) {
            int base = layer * 12;
#pragma unroll
            for (int q = 0; q < 4; q++) {       // Ry
                float c = cw[base + q], s = sw[base + q];
                int st = 1 << (3 - q);
#pragma unroll
                for (int k = 0; k < 16; k++) {
                    if (k & st) continue;
                    int k1 = k | st;
                    float ar = sr[k],  ai = si[k];
                    float br = sr[k1], bi = si[k1];
                    sr[k]  = c*ar - s*br;
                    si[k]  = c*ai - s*bi;
                    sr[k1] = s*ar + c*br;
                    si[k1] = s*ai + c*bi;
                }
            }
#pragma unroll
            for (int q = 0; q < 4; q++) {       // Rz
                float c = cw[base + 4 + q], s = sw[base + 4 + q];
                int st = 1 << (3 - q);
#pragma unroll
                for (int k = 0; k < 16; k++) {
                    float ar = sr[k], ai = si[k];
                    if (k & st) {
                        sr[k] = ar*c - ai*s;
                        si[k] = ai*c + ar*s;
                    } else {
                        sr[k] = ar*c + ai*s;
                        si[k] = ai*c - ar*s;
                    }
                }
            }
#pragma unroll
            for (int q = 0; q < 4; q++) {       // Ry
                float c = cw[base + 8 + q], s = sw[base + 8 + q];
                int st = 1 << (3 - q);
#pragma unroll
                for (int k = 0; k < 16; k++) {
                    if (k & st) continue;
                    int k1 = k | st;
                    float ar = sr[k],  ai = si[k];
                    float br = sr[k1], bi = si[k1];
                    sr[k]  = c*ar - s*br;
                    si[k]  = c*ai - s*bi;
                    sr[k1] = s*ar + c*br;
                    si[k1] = s*ai + c*bi;
                }
            }
            if (layer < 4) {                    // ring CNOTs
#pragma unroll
                for (int q = 0; q < 4; q++) {
                    int cmask = 1 << (3 - q);
                    int tmask = 1 << (3 - ((q + 1) & 3));
#pragma unroll
                    for (int k = 0; k < 16; k++) {
                        if ((k & cmask) && !(k & tmask)) {
                            int k1 = k | tmask;
                            float tr = sr[k]; sr[k] = sr[k1]; sr[k1] = tr;
                            float ti = si[k]; si[k] = si[k1]; si[k1] = ti;
                        }
                    }
                }
            }
        }

        // <Z_q> expectations -> smem
        float prob[16];
#pragma unroll
        for (int k = 0; k < 16; k++) prob[k] = sr[k]*sr[k] + si[k]*si[k];
#pragma unroll
        for (int q = 0; q < 4; q++) {
            int mask = 1 << (3 - q);
            float e = 0.0f;
#pragma unroll
            for (int k = 0; k < 16; k++)
                e += (k & mask) ? -prob[k] : prob[k];
            feat_s[t * 4 + q] = e;
        }
    } else if (t >= 224) {
        // ---------------- Phase 1b: L1 prefetch of FC weights ---------------
        int pt = t - 224;                 // 0..287
        const char* base1 = (const char*)fc1_w;
        // fc1_w: 64*784*4 = 200704 B = 1568 lines of 128 B
#pragma unroll
        for (int line = pt; line < 1568; line += 288)
            asm volatile("prefetch.global.L1 [%0];" :: "l"(base1 + (size_t)line * 128));
        if (pt < 20)                      // fc2_w: 2560 B
            asm volatile("prefetch.global.L1 [%0];" :: "l"((const char*)fc2_w + (size_t)pt * 128));
    }
    __syncthreads();

    // ---------------- Phase 2: FC1 (8 threads / neuron) + ReLU --------------
    {
        const float4* fs4 = (const float4*)feat_s;
        int neuron = t >> 3;        // 0..63
        int part   = t & 7;         // 0..7
        const float4* wr = (const float4*)(fc1_w + neuron * FEAT);
        float ax = 0.0f, ay = 0.0f, az = 0.0f, aw = 0.0f;
#pragma unroll
        for (int f = part; f < FEAT / 4; f += 8) {   // 24 or 25 iterations
            float4 wv = wr[f];
            float4 xv = fs4[f];
            ax += wv.x * xv.x;
            ay += wv.y * xv.y;
            az += wv.z * xv.z;
            aw += wv.w * xv.w;
        }
        float acc = (ax + ay) + (az + aw);
        acc += __shfl_down_sync(0xffffffffu, acc, 4, 8);
        acc += __shfl_down_sync(0xffffffffu, acc, 2, 8);
        acc += __shfl_down_sync(0xffffffffu, acc, 1, 8);
        if (part == 0) h_s[neuron] = fmaxf(acc + fc1_b[neuron], 0.0f);
    }
    __syncthreads();

    // ---------------- Phase 3: FC2, one warp per output ---------------------
    if (t < NOUT * 32) {
        int o    = t >> 5;
        int lane = t & 31;
        const float* w2 = fc2_w + o * H1;
        float a = h_s[2*lane] * w2[2*lane] + h_s[2*lane + 1] * w2[2*lane + 1];
#pragma unroll
        for (int off = 16; off > 0; off >>= 1)
            a += __shfl_down_sync(0xffffffffu, a, off);
        if (lane == 0) out[b * NOUT + o] = a + fc2_b[o];
    }
}

extern "C" void kernel_launch(void* const* d_in, const int* in_sizes, int n_in,
                              void* d_out, int out_size)
{
    const float* x     = (const float*)d_in[0];
    const float* w     = (const float*)d_in[1];
    const float* fc1_w = (const float*)d_in[2];
    const float* fc1_b = (const float*)d_in[3];
    const float* fc2_w = (const float*)d_in[4];
    const float* fc2_b = (const float*)d_in[5];
    float* out = (float*)d_out;

    fused_kernel<<<BATCH, 512>>>(x, w, fc1_w, fc1_b, fc2_w, fc2_b, out);
}

// round 8
// speedup vs baseline: 1.7259x; 1.7259x over previous
#include <cuda_runtime.h>
#include <cstdint>

#define BATCH 128
#define PATCHES 196
#define FEAT 784
#define H1 64
#define NOUT 10

#define W_STRIDE 788                       // floats per padded weight row (784+4)
#define SMEM_W_BYTES (H1 * W_STRIDE * 4)   // 201728

// smem byte offsets
#define OFF_W      0
#define OFF_FEAT   (SMEM_W_BYTES)              // 784 floats
#define OFF_PART   (OFF_FEAT + FEAT * 4)       // 8*64 floats
#define OFF_H      (OFF_PART + 8 * H1 * 4)     // 64 floats
#define OFF_CW     (OFF_H + H1 * 4)            // 12 floats (layer-0 cos)
#define OFF_SW     (OFF_CW + 12 * 4)           // 12 floats (layer-0 sin)
#define OFF_AB     (OFF_SW + 12 * 4)           // 12 gates * 4 floats (alpha,beta)
#define OFF_OBS    (OFF_AB + 48 * 4)           // 4 qubits * 3 floats (A,BR,BI)
#define OFF_MBAR   (OFF_OBS + 12 * 4)          // 8 bytes, 8-aligned
#define SMEM_TOTAL (OFF_MBAR + 16)

__device__ __forceinline__ uint32_t saddr(const void* p) {
    return (uint32_t)__cvta_generic_to_shared(p);
}

__global__ void __launch_bounds__(512) fused_kernel(
    const float* __restrict__ x, const float* __restrict__ w,
    const float* __restrict__ fc1_w, const float* __restrict__ fc1_b,
    const float* __restrict__ fc2_w, const float* __restrict__ fc2_b,
    float* __restrict__ out)
{
    extern __shared__ char smem[];
    float* wsm    = (float*)(smem + OFF_W);
    float* feat_s = (float*)(smem + OFF_FEAT);
    float* part_s = (float*)(smem + OFF_PART);
    float* h_s    = (float*)(smem + OFF_H);
    float* cw     = (float*)(smem + OFF_CW);
    float* sw     = (float*)(smem + OFF_SW);
    float* ab     = (float*)(smem + OFF_AB);
    float* obs    = (float*)(smem + OFF_OBS);
    uint32_t mbar = saddr(smem + OFF_MBAR);

    int b = blockIdx.x;
    int t = threadIdx.x;

    // ---- per-block precompute (different warps, no cross-dependence) ----
    if (t < 12) {                       // layer-0 gate angles
        float s, c;
        sincosf(0.5f * w[t], &s, &c);
        cw[t] = c; sw[t] = s;
    } else if (t >= 32 && t < 44) {     // layers 1..3 folded SU(2): U=Ry3*Rz*Ry1
        int idx = t - 32;
        int l = idx >> 2, q = idx & 3;
        int base = (l + 1) * 12;
        float c1, s1, c2, s2, c3, s3;
        sincosf(0.5f * w[base + q],     &s1, &c1);
        sincosf(0.5f * w[base + 4 + q], &s2, &c2);
        sincosf(0.5f * w[base + 8 + q], &s3, &c3);
        float* o = ab + idx * 4;
        o[0] =  c2 * (c3 * c1 - s3 * s1);   // alpha_r
        o[1] = -s2 * (c3 * c1 + s3 * s1);   // alpha_i
        o[2] =  c2 * (s3 * c1 + c3 * s1);   // beta_r
        o[3] =  s2 * (c3 * s1 - s3 * c1);   // beta_i
    } else if (t >= 64 && t < 68) {     // layer-4 + <Z_q> folded observable
        int q = t - 64;
        float c1, s1, c2, s2, c3, s3;
        sincosf(0.5f * w[48 + q], &s1, &c1);
        sincosf(0.5f * w[52 + q], &s2, &c2);
        sincosf(0.5f * w[56 + q], &s3, &c3);
        float ar =  c2 * (c3 * c1 - s3 * s1);
        float ai = -s2 * (c3 * c1 + s3 * s1);
        float br =  c2 * (s3 * c1 + c3 * s1);
        float bi =  s2 * (c3 * s1 - s3 * c1);
        obs[q * 3 + 0] = ar * ar + ai * ai - br * br - bi * bi;  // A
        obs[q * 3 + 1] = 4.0f * (ai * bi - ar * br);             // BR
        obs[q * 3 + 2] = 4.0f * (ar * bi + ai * br);             // BI
    } else if (t == 511) {              // mbarrier init for the weight DMA
        asm volatile("mbarrier.init.shared.b64 [%0], 1;" :: "r"(mbar) : "memory");
    }
    __syncthreads();

    // ---- kick off fc1_w -> smem bulk copy (overlaps with circuit phase) ----
    if (t == 511) {
        asm volatile("mbarrier.arrive.expect_tx.shared.b64 _, [%0], %1;"
                     :: "r"(mbar), "r"(64u * 3136u) : "memory");
        for (int n = 0; n < 64; n++) {
            uint32_t dst = saddr(wsm + n * W_STRIDE);
            const float* src = fc1_w + n * FEAT;
            asm volatile(
                "cp.async.bulk.shared::cta.global.mbarrier::complete_tx::bytes "
                "[%0], [%1], %2, [%3];"
                :: "r"(dst), "l"(src), "r"(3136u), "r"(mbar) : "memory");
        }
    }

    // ---------------- Phase 1: circuit, one patch per thread ----------------
    if (t < PATCHES) {
        int i = t / 14;
        int j = t % 14;
        const float* xb = x + b * FEAT;
        const float PI_F = 3.14159265358979323846f;   // (2*pi*x)/2
        float angs[4];
        angs[0] = PI_F * xb[(2*i)  *28 + 2*j    ];
        angs[1] = PI_F * xb[(2*i)  *28 + 2*j + 1];
        angs[2] = PI_F * xb[(2*i+1)*28 + 2*j    ];
        angs[3] = PI_F * xb[(2*i+1)*28 + 2*j + 1];

        // per-qubit 2-amp states through Rx + layer-0 Ry,Rz,Ry (product state)
        float a0r[4], a0i[4], a1r[4], a1i[4];
#pragma unroll
        for (int q = 0; q < 4; q++) {
            float s, c;
            __sincosf(angs[q], &s, &c);
            float xr0 = c,    xi0 = 0.0f;
            float xr1 = 0.0f, xi1 = -s;
            float c1 = cw[q], s1 = sw[q];
            float yr0 = c1*xr0 - s1*xr1, yi0 = c1*xi0 - s1*xi1;
            float yr1 = s1*xr0 + c1*xr1, yi1 = s1*xi0 + c1*xi1;
            float c2 = cw[4+q], s2 = sw[4+q];
            float zr0 = yr0*c2 + yi0*s2, zi0 = yi0*c2 - yr0*s2;
            float zr1 = yr1*c2 - yi1*s2, zi1 = yi1*c2 + yr1*s2;
            float c3 = cw[8+q], s3 = sw[8+q];
            a0r[q] = c3*zr0 - s3*zr1;  a0i[q] = c3*zi0 - s3*zi1;
            a1r[q] = s3*zr0 + c3*zr1;  a1i[q] = s3*zi0 + c3*zi1;
        }

        // tensor up to 16 amps
        float ur[4], ui[4], vr[4], vi[4];
#pragma unroll
        for (int i0 = 0; i0 < 2; i0++)
#pragma unroll
            for (int i1 = 0; i1 < 2; i1++) {
                float xr = i0 ? a1r[0] : a0r[0], xi = i0 ? a1i[0] : a0i[0];
                float yr = i1 ? a1r[1] : a0r[1], yi = i1 ? a1i[1] : a0i[1];
                ur[i0*2+i1] = xr*yr - xi*yi;
                ui[i0*2+i1] = xr*yi + xi*yr;
                float zr = i0 ? a1r[2] : a0r[2], zi = i0 ? a1i[2] : a0i[2];
                float wr2 = i1 ? a1r[3] : a0r[3], wi2 = i1 ? a1i[3] : a0i[3];
                vr[i0*2+i1] = zr*wr2 - zi*wi2;
                vi[i0*2+i1] = zr*wi2 + zi*wr2;
            }
        float sr[16], si[16];
#pragma unroll
        for (int k = 0; k < 16; k++) {
            float xr = ur[k >> 2], xi = ui[k >> 2];
            float yr = vr[k & 3],  yi = vi[k & 3];
            sr[k] = xr*yr - xi*yi;
            si[k] = xr*yi + xi*yr;
        }

        // ring CNOTs after layer 0 (pure register renames)
#pragma unroll
        for (int q = 0; q < 4; q++) {
            int cmask = 1 << (3 - q);
            int tmask = 1 << (3 - ((q + 1) & 3));
#pragma unroll
            for (int k = 0; k < 16; k++) {
                if ((k & cmask) && !(k & tmask)) {
                    int k1 = k | tmask;
                    float tr = sr[k]; sr[k] = sr[k1]; sr[k1] = tr;
                    float ti = si[k]; si[k] = si[k1]; si[k1] = ti;
                }
            }
        }

        // layers 1..3: one folded SU(2) gate per qubit, then ring
#pragma unroll
        for (int l = 0; l < 3; l++) {
#pragma unroll
            for (int q = 0; q < 4; q++) {
                const float* o = ab + (l * 4 + q) * 4;
                float Ar = o[0], Ai = o[1], Br = o[2], Bi = o[3];
                int st = 1 << (3 - q);
#pragma unroll
                for (int k = 0; k < 16; k++) {
                    if (k & st) continue;
                    int k1 = k | st;
                    float r0 = sr[k],  i0 = si[k];
                    float r1 = sr[k1], i1 = si[k1];
                    sr[k]  = Ar*r0 - Ai*i0 - Br*r1 - Bi*i1;
                    si[k]  = Ar*i0 + Ai*r0 - Br*i1 + Bi*r1;
                    sr[k1] = Br*r0 - Bi*i0 + Ar*r1 + Ai*i1;
                    si[k1] = Br*i0 + Bi*r0 + Ar*i1 - Ai*r1;
                }
            }
#pragma unroll
            for (int q = 0; q < 4; q++) {
                int cmask = 1 << (3 - q);
                int tmask = 1 << (3 - ((q + 1) & 3));
#pragma unroll
                for (int k = 0; k < 16; k++) {
                    if ((k & cmask) && !(k & tmask)) {
                        int k1 = k | tmask;
                        float tr = sr[k]; sr[k] = sr[k1]; sr[k1] = tr;
                        float ti = si[k]; si[k] = si[k1]; si[k1] = ti;
                    }
                }
            }
        }

        // layer 4 + <Z_q> folded: e_q = sum_pairs A(p0-p1) + BR*X - BI*Y
        float p[16];
#pragma unroll
        for (int k = 0; k < 16; k++) p[k] = sr[k]*sr[k] + si[k]*si[k];
#pragma unroll
        for (int q = 0; q < 4; q++) {
            int st = 1 << (3 - q);
            float A  = obs[q * 3 + 0];
            float BR = obs[q * 3 + 1];
            float BI = obs[q * 3 + 2];
            float e = 0.0f;
#pragma unroll
            for (int k = 0; k < 16; k++) {
                if (k & st) continue;
                int k1 = k | st;
                float X = sr[k]*sr[k1] + si[k]*si[k1];
                float Y = sr[k]*si[k1] - si[k]*sr[k1];
                e += A * (p[k] - p[k1]) + BR * X - BI * Y;
            }
            feat_s[t * 4 + q] = e;
        }
    }
    __syncthreads();   // feat_s ready

    // wait for fc1_w DMA (normally long done — overlapped with circuit)
    {
        asm volatile(
            "{\n\t.reg .pred p;\n\t"
            "WAITLP_%=:\n\t"
            "mbarrier.try_wait.parity.acquire.cta.shared::cta.b64 p, [%0], 0, 0x989680;\n\t"
            "@!p bra WAITLP_%=;\n\t}"
            :: "r"(mbar) : "memory");
    }

    // ---------------- Phase 2: FC1 from smem weights ------------------------
    {
        int neuron = t & 63;
        int part   = t >> 6;                 // constant per warp -> feat broadcast
        const float4* ws4 = (const float4*)(wsm + neuron * W_STRIDE);
        const float4* fs4 = (const float4*)feat_s;
        float ax = 0.0f, ay = 0.0f, az = 0.0f, aw2 = 0.0f;
#pragma unroll
        for (int f = part; f < FEAT / 4; f += 8) {
            float4 wv = ws4[f];
            float4 xv = fs4[f];
            ax  += wv.x * xv.x;
            ay  += wv.y * xv.y;
            az  += wv.z * xv.z;
            aw2 += wv.w * xv.w;
        }
        part_s[part * 64 + neuron] = (ax + ay) + (az + aw2);
    }
    __syncthreads();

    if (t < H1) {
        float a = fc1_b[t];
#pragma unroll
        for (int p8 = 0; p8 < 8; p8++) a += part_s[p8 * 64 + t];
        h_s[t] = fmaxf(a, 0.0f);
    }
    __syncthreads();

    // ---------------- Phase 3: FC2, one warp per output ---------------------
    if (t < NOUT * 32) {
        int o    = t >> 5;
        int lane = t & 31;
        const float* w2 = fc2_w + o * H1;
        float a = h_s[2*lane] * w2[2*lane] + h_s[2*lane + 1] * w2[2*lane + 1];
#pragma unroll
        for (int off = 16; off > 0; off >>= 1)
            a += __shfl_down_sync(0xffffffffu, a, off);
        if (lane == 0) out[b * NOUT + o] = a + fc2_b[o];
    }
}

extern "C" void kernel_launch(void* const* d_in, const int* in_sizes, int n_in,
                              void* d_out, int out_size)
{
    const float* x     = (const float*)d_in[0];
    const float* w     = (const float*)d_in[1];
    const float* fc1_w = (const float*)d_in[2];
    const float* fc1_b = (const float*)d_in[3];
    const float* fc2_w = (const float*)d_in[4];
    const float* fc2_b = (const float*)d_in[5];
    float* out = (float*)d_out;

    cudaFuncSetAttribute(fused_kernel,
                         cudaFuncAttributeMaxDynamicSharedMemorySize, SMEM_TOTAL);
    fused_kernel<<<BATCH, 512, SMEM_TOTAL>>>(x, w, fc1_w, fc1_b, fc2_w, fc2_b, out);
}

// round 10
// speedup vs baseline: 1.7672x; 1.0239x over previous
#include <cuda_runtime.h>
#include <cstdint>

#define BATCH 128
#define PATCHES 196
#define FEAT 784
#define H1 64
#define NOUT 10

#define CLUSTER 4
#define ROWS_PER_CTA (H1 / CLUSTER)        // 16 weight rows copied per CTA

#define W_STRIDE 788                       // floats per padded weight row (784+4)
#define SMEM_W_BYTES (H1 * W_STRIDE * 4)   // 201728

// smem byte offsets
#define OFF_W      0
#define OFF_FEAT   (SMEM_W_BYTES)              // 784 floats
#define OFF_PART   (OFF_FEAT + FEAT * 4)       // 8*64 floats
#define OFF_H      (OFF_PART + 8 * H1 * 4)     // 64 floats
#define OFF_CW     (OFF_H + H1 * 4)            // 12 floats (layer-0 cos)
#define OFF_SW     (OFF_CW + 12 * 4)           // 12 floats (layer-0 sin)
#define OFF_AB     (OFF_SW + 12 * 4)           // 12 gates * 4 floats (alpha,beta)
#define OFF_OBS    (OFF_AB + 48 * 4)           // 4 qubits * 3 floats (A,BR,BI)
#define OFF_MBAR   (OFF_OBS + 12 * 4)          // 8 bytes, 8-aligned
#define SMEM_TOTAL (OFF_MBAR + 16)

__device__ __forceinline__ uint32_t saddr(const void* p) {
    return (uint32_t)__cvta_generic_to_shared(p);
}

__global__ void __launch_bounds__(512) __cluster_dims__(CLUSTER, 1, 1)
fused_kernel(
    const float* __restrict__ x, const float* __restrict__ w,
    const float* __restrict__ fc1_w, const float* __restrict__ fc1_b,
    const float* __restrict__ fc2_w, const float* __restrict__ fc2_b,
    float* __restrict__ out)
{
    extern __shared__ char smem[];
    float* wsm    = (float*)(smem + OFF_W);
    float* feat_s = (float*)(smem + OFF_FEAT);
    float* part_s = (float*)(smem + OFF_PART);
    float* h_s    = (float*)(smem + OFF_H);
    float* cw     = (float*)(smem + OFF_CW);
    float* sw     = (float*)(smem + OFF_SW);
    float* ab     = (float*)(smem + OFF_AB);
    float* obs    = (float*)(smem + OFF_OBS);
    uint32_t mbar = saddr(smem + OFF_MBAR);

    int b = blockIdx.x;
    int t = threadIdx.x;

    // ---- per-block precompute (different warps, no cross-dependence) ----
    if (t < 12) {                       // layer-0 gate angles
        float s, c;
        __sincosf(0.5f * w[t], &s, &c);
        cw[t] = c; sw[t] = s;
    } else if (t >= 32 && t < 44) {     // layers 1..3 folded SU(2): U=Ry3*Rz*Ry1
        int idx = t - 32;
        int l = idx >> 2, q = idx & 3;
        int base = (l + 1) * 12;
        float c1, s1, c2, s2, c3, s3;
        __sincosf(0.5f * w[base + q],     &s1, &c1);
        __sincosf(0.5f * w[base + 4 + q], &s2, &c2);
        __sincosf(0.5f * w[base + 8 + q], &s3, &c3);
        float* o = ab + idx * 4;
        o[0] =  c2 * (c3 * c1 - s3 * s1);   // alpha_r
        o[1] = -s2 * (c3 * c1 + s3 * s1);   // alpha_i
        o[2] =  c2 * (s3 * c1 + c3 * s1);   // beta_r
        o[3] =  s2 * (c3 * s1 - s3 * c1);   // beta_i
    } else if (t >= 64 && t < 68) {     // layer-4 + <Z_q> folded observable
        int q = t - 64;
        float c1, s1, c2, s2, c3, s3;
        __sincosf(0.5f * w[48 + q], &s1, &c1);
        __sincosf(0.5f * w[52 + q], &s2, &c2);
        __sincosf(0.5f * w[56 + q], &s3, &c3);
        float ar =  c2 * (c3 * c1 - s3 * s1);
        float ai = -s2 * (c3 * c1 + s3 * s1);
        float br =  c2 * (s3 * c1 + c3 * s1);
        float bi =  s2 * (c3 * s1 - s3 * c1);
        obs[q * 3 + 0] = ar * ar + ai * ai - br * br - bi * bi;  // A
        obs[q * 3 + 1] = 4.0f * (ai * bi - ar * br);             // BR
        obs[q * 3 + 2] = 4.0f * (ar * bi + ai * br);             // BI
    } else if (t == 511) {              // mbarrier init for the weight DMA
        asm volatile("mbarrier.init.shared.b64 [%0], 1;" :: "r"(mbar) : "memory");
    }
    __syncthreads();

    // ---- cluster-wide: barriers initialized before any multicast lands ----
    asm volatile("barrier.cluster.arrive.aligned;" ::: "memory");
    asm volatile("barrier.cluster.wait.aligned;"   ::: "memory");

    // ---- kick off fc1_w -> smem multicast copy (overlaps circuit phase) ----
    // Each cluster CTA copies its 16 rows, multicast to all 4 CTAs.
    if (t == 511) {
        uint32_t rank;
        asm("mov.u32 %0, %%cluster_ctarank;" : "=r"(rank));
        asm volatile("mbarrier.arrive.expect_tx.shared.b64 _, [%0], %1;"
                     :: "r"(mbar), "r"((uint32_t)(H1 * 3136u)) : "memory");
        const uint16_t mask = (1u << CLUSTER) - 1u;
        int row0 = rank * ROWS_PER_CTA;
        for (int n = row0; n < row0 + ROWS_PER_CTA; n++) {
            uint32_t dst = saddr(wsm + n * W_STRIDE);
            const float* src = fc1_w + n * FEAT;
            asm volatile(
                "cp.async.bulk.shared::cluster.global.mbarrier::complete_tx::bytes"
                ".multicast::cluster [%0], [%1], %2, [%3], %4;"
                :: "r"(dst), "l"(src), "r"(3136u), "r"(mbar), "h"(mask) : "memory");
        }
    }

    // ---------------- Phase 1: circuit, one patch per thread ----------------
    if (t < PATCHES) {
        int i = t / 14;
        int j = t % 14;
        const float* xb = x + b * FEAT;
        const float PI_F = 3.14159265358979323846f;   // (2*pi*x)/2
        float angs[4];
        angs[0] = PI_F * xb[(2*i)  *28 + 2*j    ];
        angs[1] = PI_F * xb[(2*i)  *28 + 2*j + 1];
        angs[2] = PI_F * xb[(2*i+1)*28 + 2*j    ];
        angs[3] = PI_F * xb[(2*i+1)*28 + 2*j + 1];

        // per-qubit 2-amp states through Rx + layer-0 Ry,Rz,Ry (product state)
        float a0r[4], a0i[4], a1r[4], a1i[4];
#pragma unroll
        for (int q = 0; q < 4; q++) {
            float s, c;
            __sincosf(angs[q], &s, &c);
            float xr0 = c,    xi0 = 0.0f;
            float xr1 = 0.0f, xi1 = -s;
            float c1 = cw[q], s1 = sw[q];
            float yr0 = c1*xr0 - s1*xr1, yi0 = c1*xi0 - s1*xi1;
            float yr1 = s1*xr0 + c1*xr1, yi1 = s1*xi0 + c1*xi1;
            float c2 = cw[4+q], s2 = sw[4+q];
            float zr0 = yr0*c2 + yi0*s2, zi0 = yi0*c2 - yr0*s2;
            float zr1 = yr1*c2 - yi1*s2, zi1 = yi1*c2 + yr1*s2;
            float c3 = cw[8+q], s3 = sw[8+q];
            a0r[q] = c3*zr0 - s3*zr1;  a0i[q] = c3*zi0 - s3*zi1;
            a1r[q] = s3*zr0 + c3*zr1;  a1i[q] = s3*zi0 + c3*zi1;
        }

        // tensor up to 16 amps
        float ur[4], ui[4], vr[4], vi[4];
#pragma unroll
        for (int i0 = 0; i0 < 2; i0++)
#pragma unroll
            for (int i1 = 0; i1 < 2; i1++) {
                float xr = i0 ? a1r[0] : a0r[0], xi = i0 ? a1i[0] : a0i[0];
                float yr = i1 ? a1r[1] : a0r[1], yi = i1 ? a1i[1] : a0i[1];
                ur[i0*2+i1] = xr*yr - xi*yi;
                ui[i0*2+i1] = xr*yi + xi*yr;
                float zr = i0 ? a1r[2] : a0r[2], zi = i0 ? a1i[2] : a0i[2];
                float wr2 = i1 ? a1r[3] : a0r[3], wi2 = i1 ? a1i[3] : a0i[3];
                vr[i0*2+i1] = zr*wr2 - zi*wi2;
                vi[i0*2+i1] = zr*wi2 + zi*wr2;
            }
        float sr[16], si[16];
#pragma unroll
        for (int k = 0; k < 16; k++) {
            float xr = ur[k >> 2], xi = ui[k >> 2];
            float yr = vr[k & 3],  yi = vi[k & 3];
            sr[k] = xr*yr - xi*yi;
            si[k] = xr*yi + xi*yr;
        }

        // ring CNOTs after layer 0 (pure register renames)
#pragma unroll
        for (int q = 0; q < 4; q++) {
            int cmask = 1 << (3 - q);
            int tmask = 1 << (3 - ((q + 1) & 3));
#pragma unroll
            for (int k = 0; k < 16; k++) {
                if ((k & cmask) && !(k & tmask)) {
                    int k1 = k | tmask;
                    float tr = sr[k]; sr[k] = sr[k1]; sr[k1] = tr;
                    float ti = si[k]; si[k] = si[k1]; si[k1] = ti;
                }
            }
        }

        // layers 1..3: one folded SU(2) gate per qubit, then ring
#pragma unroll
        for (int l = 0; l < 3; l++) {
#pragma unroll
            for (int q = 0; q < 4; q++) {
                const float* o = ab + (l * 4 + q) * 4;
                float Ar = o[0], Ai = o[1], Br = o[2], Bi = o[3];
                int st = 1 << (3 - q);
#pragma unroll
                for (int k = 0; k < 16; k++) {
                    if (k & st) continue;
                    int k1 = k | st;
                    float r0 = sr[k],  i0 = si[k];
                    float r1 = sr[k1], i1 = si[k1];
                    sr[k]  = Ar*r0 - Ai*i0 - Br*r1 - Bi*i1;
                    si[k]  = Ar*i0 + Ai*r0 - Br*i1 + Bi*r1;
                    sr[k1] = Br*r0 - Bi*i0 + Ar*r1 + Ai*i1;
                    si[k1] = Br*i0 + Bi*r0 + Ar*i1 - Ai*r1;
                }
            }
#pragma unroll
            for (int q = 0; q < 4; q++) {
                int cmask = 1 << (3 - q);
                int tmask = 1 << (3 - ((q + 1) & 3));
#pragma unroll
                for (int k = 0; k < 16; k++) {
                    if ((k & cmask) && !(k & tmask)) {
                        int k1 = k | tmask;
                        float tr = sr[k]; sr[k] = sr[k1]; sr[k1] = tr;
                        float ti = si[k]; si[k] = si[k1]; si[k1] = ti;
                    }
                }
            }
        }

        // layer 4 + <Z_q> folded: e_q = sum_pairs A(p0-p1) + BR*X - BI*Y
        float p[16];
#pragma unroll
        for (int k = 0; k < 16; k++) p[k] = sr[k]*sr[k] + si[k]*si[k];
#pragma unroll
        for (int q = 0; q < 4; q++) {
            int st = 1 << (3 - q);
            float A  = obs[q * 3 + 0];
            float BR = obs[q * 3 + 1];
            float BI = obs[q * 3 + 2];
            float e = 0.0f;
#pragma unroll
            for (int k = 0; k < 16; k++) {
                if (k & st) continue;
                int k1 = k | st;
                float X = sr[k]*sr[k1] + si[k]*si[k1];
                float Y = sr[k]*si[k1] - si[k]*sr[k1];
                e += A * (p[k] - p[k1]) + BR * X - BI * Y;
            }
            feat_s[t * 4 + q] = e;
        }
    }
    __syncthreads();   // feat_s ready

    // wait for fc1_w DMA (normally long done — overlapped with circuit)
    {
        asm volatile(
            "{\n\t.reg .pred p;\n\t"
            "WAITLP_%=:\n\t"
            "mbarrier.try_wait.parity.acquire.cta.shared::cta.b64 p, [%0], 0, 0x989680;\n\t"
            "@!p bra WAITLP_%=;\n\t}"
            :: "r"(mbar) : "memory");
    }

    // ---------------- Phase 2: FC1 from smem weights ------------------------
    {
        int neuron = t & 63;
        int part   = t >> 6;                 // constant per warp -> feat broadcast
        const float4* ws4 = (const float4*)(wsm + neuron * W_STRIDE);
        const float4* fs4 = (const float4*)feat_s;
        float ax = 0.0f, ay = 0.0f, az = 0.0f, aw2 = 0.0f;
#pragma unroll
        for (int f = part; f < FEAT / 4; f += 8) {
            float4 wv = ws4[f];
            float4 xv = fs4[f];
            ax  += wv.x * xv.x;
            ay  += wv.y * xv.y;
            az  += wv.z * xv.z;
            aw2 += wv.w * xv.w;
        }
        part_s[part * 64 + neuron] = (ax + ay) + (az + aw2);
    }
    __syncthreads();

    if (t < H1) {
        float a = fc1_b[t];
#pragma unroll
        for (int p8 = 0; p8 < 8; p8++) a += part_s[p8 * 64 + t];
        h_s[t] = fmaxf(a, 0.0f);
    }
    __syncthreads();

    // ---------------- Phase 3: FC2, one warp per output ---------------------
    if (t < NOUT * 32) {
        int o    = t >> 5;
        int lane = t & 31;
        const float* w2 = fc2_w + o * H1;
        float a = h_s[2*lane] * w2[2*lane] + h_s[2*lane + 1] * w2[2*lane + 1];
#pragma unroll
        for (int off = 16; off > 0; off >>= 1)
            a += __shfl_down_sync(0xffffffffu, a, off);
        if (lane == 0) out[b * NOUT + o] = a + fc2_b[o];
    }
}

extern "C" void kernel_launch(void* const* d_in, const int* in_sizes, int n_in,
                              void* d_out, int out_size)
{
    const float* x     = (const float*)d_in[0];
    const float* w     = (const float*)d_in[1];
    const float* fc1_w = (const float*)d_in[2];
    const float* fc1_b = (const float*)d_in[3];
    const float* fc2_w = (const float*)d_in[4];
    const float* fc2_b = (const float*)d_in[5];
    float* out = (float*)d_out;

    cudaFuncSetAttribute(fused_kernel,
                         cudaFuncAttributeMaxDynamicSharedMemorySize, SMEM_TOTAL);
    fused_kernel<<<BATCH, 512, SMEM_TOTAL>>>(x, w, fc1_w, fc1_b, fc2_w, fc2_b, out);
}